// round 11
// baseline (speedup 1.0000x reference)
#include <cuda_runtime.h>
#include <cuda_bf16.h>
#include <cstdint>

// CenterLossLayer: B=16384, C=1024, D=512, alpha=0.5
//   result[b]   = sum_d (features[b,d] - centers[labels[b],d])^2
//   delta[c,d]  = sum_{b: labels[b]==c} (centers[c,d] - features[b,d])
//   new_centers = centers - alpha * delta / (count_c + 1)
// d_out: [0..B) result f32 ; [B .. B+C*D) new_centers f32
//
// Single launch, G=4 classes/block, NREP=2 replica warps per class.
// Feature rows streamed via cp.async into a per-warp 4-stage smem ring:
// loads stay continuously in flight (register-free MLP), compute from smem.

#define BATCH       16384
#define NUM_CLASSES 1024
#define FEAT_DIM    512
#define ALPHA       0.5f

#define G        4
#define THREADS  256
#define NWARPS   (THREADS / 32)    // 8
#define NREP     (NWARPS / G)      // 2
#define CAPG     64
#define NF4      (FEAT_DIM / 4)    // 128
#define NSTAGE   4                 // smem ring depth per warp (4 x 2KB)

// dynamic smem layout (floats):
//   [0                .. G*FEAT_DIM)                    s_centers (8 KB)
//   [G*FEAT_DIM       .. +G*NREP*FEAT_DIM)              s_delta   (16 KB)
//   [..               .. +NWARPS*NSTAGE*FEAT_DIM)       s_feat ring (64 KB)
#define OFF_CENTERS 0
#define OFF_DELTA   (G * FEAT_DIM)                        // 2048
#define OFF_FEAT    (OFF_DELTA + G * NREP * FEAT_DIM)     // 6144
#define SMEM_FLOATS (OFF_FEAT + NWARPS * NSTAGE * FEAT_DIM)
#define SMEM_BYTES  (SMEM_FLOATS * 4)                     // 90112 B = 88 KB

#define F4_ZERO make_float4(0.f, 0.f, 0.f, 0.f)

__device__ __forceinline__ float4 f4_sub(float4 a, float4 b) {
    return make_float4(a.x - b.x, a.y - b.y, a.z - b.z, a.w - b.w);
}
__device__ __forceinline__ void f4_acc(float4& a, float4 b) {
    a.x += b.x; a.y += b.y; a.z += b.z; a.w += b.w;
}
__device__ __forceinline__ float f4_dot(float4 a) {
    return a.x * a.x + a.y * a.y + a.z * a.z + a.w * a.w;
}

__device__ __forceinline__ void cp_async16(uint32_t dst_smem, const void* src) {
    asm volatile("cp.async.cg.shared.global [%0], [%1], 16;\n"
                 :: "r"(dst_smem), "l"(src) : "memory");
}
__device__ __forceinline__ void cp_commit() {
    asm volatile("cp.async.commit_group;\n" ::: "memory");
}
template <int N>
__device__ __forceinline__ void cp_wait() {
    asm volatile("cp.async.wait_group %0;\n" :: "n"(N) : "memory");
}

__global__ __launch_bounds__(THREADS, 2)
void center_loss_fused_kernel(const float* __restrict__ features,
                              const float* __restrict__ centers,
                              const int*   __restrict__ labels,
                              float*       __restrict__ out_result,
                              float*       __restrict__ out_centers) {
    extern __shared__ __align__(16) float smem[];
    float* s_centers = smem + OFF_CENTERS;
    float* s_delta   = smem + OFF_DELTA;
    float* s_feat    = smem + OFF_FEAT;

    __shared__ int s_list[G][CAPG];
    __shared__ int s_gcnt[G];

    const int t  = threadIdx.x;
    const int c0 = blockIdx.x * G;

    if (t < G) s_gcnt[t] = 0;
    {   // load G center rows: 512 float4s, 256 threads -> 2 each
        const float4* src = reinterpret_cast<const float4*>(centers + (size_t)c0 * FEAT_DIM);
        float4* dst = reinterpret_cast<float4*>(s_centers);
        dst[t]           = src[t];
        dst[t + THREADS] = src[t + THREADS];
    }
    __syncthreads();

    // ---- scan labels once per block (64 KB, L2-resident chip-wide) ----
    const int4* lab4 = reinterpret_cast<const int4*>(labels);
    #pragma unroll
    for (int i = 0; i < BATCH / 4 / THREADS; i++) {        // 16 iterations
        int idx4 = i * THREADS + t;
        int4 L = lab4[idx4];
        int b0 = idx4 * 4;
        int ls[4] = {L.x, L.y, L.z, L.w};
        #pragma unroll
        for (int j = 0; j < 4; j++) {
            int g = ls[j] - c0;
            if ((unsigned)g < (unsigned)G) {
                int pos = atomicAdd(&s_gcnt[g], 1);
                if (pos < CAPG) s_list[g][pos] = b0 + j;
            }
        }
    }
    __syncthreads();

    // ---- warp-per-class (2 replicas), cp.async 4-stage pipeline ----
    const int warp = t >> 5;
    const int lane = t & 31;
    const int g    = warp & (G - 1);
    const int r    = warp >> 2;
    const int cnt  = min(s_gcnt[g], CAPG);
    // number of samples for this warp: indices r, r+NREP, ...
    const int nw = (cnt > r) ? ((cnt - r + NREP - 1) / NREP) : 0;

    // center row cached in registers (this lane's 16 floats)
    const float4* cen4 = reinterpret_cast<const float4*>(s_centers + g * FEAT_DIM);
    const float4 c0v = cen4[lane +  0];
    const float4 c1v = cen4[lane + 32];
    const float4 c2v = cen4[lane + 64];
    const float4 c3v = cen4[lane + 96];

    float4 a0 = F4_ZERO, a1 = F4_ZERO, a2 = F4_ZERO, a3 = F4_ZERO;

    // ring base for this warp (smem address space)
    float* ring = s_feat + (size_t)warp * NSTAGE * FEAT_DIM;

    // prologue: fill up to NSTAGE stages (one commit group per stage, empty ok)
    #pragma unroll
    for (int p = 0; p < NSTAGE; p++) {
        if (p < nw) {
            int b = s_list[g][r + p * NREP];
            const float* src = features + (size_t)b * FEAT_DIM;
            uint32_t dst = (uint32_t)__cvta_generic_to_shared(ring + p * FEAT_DIM);
            cp_async16(dst + lane * 16,                src + lane * 4);
            cp_async16(dst + (lane + 32) * 16,         src + (lane + 32) * 4);
            cp_async16(dst + (lane + 64) * 16,         src + (lane + 64) * 4);
            cp_async16(dst + (lane + 96) * 16,         src + (lane + 96) * 4);
        }
        cp_commit();
    }

    for (int k = 0; k < nw; k++) {
        cp_wait<NSTAGE - 1>();     // group k complete (NSTAGE+k committed so far)

        int b_cur = s_list[g][r + k * NREP];
        const float4* slot = reinterpret_cast<const float4*>(
            ring + (k % NSTAGE) * FEAT_DIM);
        float4 f0 = slot[lane];
        float4 f1 = slot[lane + 32];
        float4 f2 = slot[lane + 64];
        float4 f3 = slot[lane + 96];

        float4 d0 = f4_sub(c0v, f0);
        float4 d1 = f4_sub(c1v, f1);
        float4 d2 = f4_sub(c2v, f2);
        float4 d3 = f4_sub(c3v, f3);
        f4_acc(a0, d0); f4_acc(a1, d1); f4_acc(a2, d2); f4_acc(a3, d3);
        float sq = f4_dot(d0) + f4_dot(d1) + f4_dot(d2) + f4_dot(d3);

        #pragma unroll
        for (int off = 16; off > 0; off >>= 1)
            sq += __shfl_xor_sync(0xFFFFFFFFu, sq, off);
        if (lane == 0) out_result[b_cur] = sq;

        // refill the slot we just consumed (issued AFTER reads: same-thread
        // LSU ordering + asm memory clobber prevent WAR on the slot)
        int p = k + NSTAGE;
        if (p < nw) {
            int b = s_list[g][r + p * NREP];
            const float* src = features + (size_t)b * FEAT_DIM;
            uint32_t dst = (uint32_t)__cvta_generic_to_shared(
                ring + (p % NSTAGE) * FEAT_DIM);
            cp_async16(dst + lane * 16,                src + lane * 4);
            cp_async16(dst + (lane + 32) * 16,         src + (lane + 32) * 4);
            cp_async16(dst + (lane + 64) * 16,         src + (lane + 64) * 4);
            cp_async16(dst + (lane + 96) * 16,         src + (lane + 96) * 4);
        }
        cp_commit();
    }

    // write replica accumulator (plain STS, full coverage — no init needed)
    float4* dd = reinterpret_cast<float4*>(s_delta + (size_t)(g * NREP + r) * FEAT_DIM);
    dd[lane] = a0; dd[lane + 32] = a1; dd[lane + 64] = a2; dd[lane + 96] = a3;
    __syncthreads();

    // ---- finalize: reduce 2 replicas; new_centers = centers - a*delta/(cnt+1)
    #pragma unroll
    for (int k = 0; k < 2; k++) {
        int idx = k * THREADS + t;         // 0..511
        int gg  = idx / NF4;
        int q   = idx % NF4;
        float s = ALPHA / (float)(s_gcnt[gg] + 1);

        const float4* base = reinterpret_cast<const float4*>(s_delta);
        float4 acc = base[(gg * NREP + 0) * NF4 + q];
        f4_acc(acc, base[(gg * NREP + 1) * NF4 + q]);

        float4 ce = reinterpret_cast<const float4*>(s_centers)[idx];
        float4 o;
        o.x = ce.x - s * acc.x;
        o.y = ce.y - s * acc.y;
        o.z = ce.z - s * acc.z;
        o.w = ce.w - s * acc.w;
        reinterpret_cast<float4*>(out_centers + (size_t)c0 * FEAT_DIM)[idx] = o;
    }
}

// ---------------------------------------------------------------------------
extern "C" void kernel_launch(void* const* d_in, const int* in_sizes, int n_in,
                              void* d_out, int out_size) {
    const float* features = (const float*)d_in[0];
    const float* centers  = (const float*)d_in[1];
    const int*   labels   = (const int*)d_in[2];

    float* out_result      = (float*)d_out;          // [BATCH]
    float* out_new_centers = (float*)d_out + BATCH;  // [NUM_CLASSES * FEAT_DIM]

    cudaFuncSetAttribute(center_loss_fused_kernel,
                         cudaFuncAttributeMaxDynamicSharedMemorySize, SMEM_BYTES);

    center_loss_fused_kernel<<<NUM_CLASSES / G, THREADS, SMEM_BYTES>>>(
        features, centers, labels, out_result, out_new_centers);
}